// round 12
// baseline (speedup 1.0000x reference)
#include <cuda_runtime.h>
#include <cuda_bf16.h>
#include <cuda_fp16.h>
#include <cstdint>

// Problem constants
#define TT   500
#define BB   128
#define CC   700
#define CP   704      // padded K
#define HH   1024
#define OO   20
#define MM   (TT*BB)  // 64000

// ---------------------------------------------------------------------------
// Device scratch
__device__ __nv_bfloat16 g_xh[(size_t)MM * CP];   // delayed input hi
__device__ __nv_bfloat16 g_xl[(size_t)MM * CP];   // delayed input lo
__device__ __nv_bfloat16 g_wh[(size_t)HH * CP];   // w_in hi  [h][k]
__device__ __nv_bfloat16 g_wl[(size_t)HH * CP];   // w_in lo
__device__ __half g_wrecH[(size_t)HH * HH];       // w_rec transposed [j][h], fp16
__device__ float g_woutT[(size_t)HH * OO];        // w_out transposed [j][o]
__device__ float g_Iin[(size_t)MM * HH];          // I_in[m][h]
__device__ int   g_done[TT];                      // per-timestep tile counters

// ---------------------------------------------------------------------------
__device__ __forceinline__ uint32_t smem_u32(const void* p) {
    uint32_t a;
    asm("{ .reg .u64 t; cvta.to.shared.u64 t, %1; cvt.u32.u64 %0, t; }" : "=r"(a) : "l"(p));
    return a;
}
#define CP16(dst, src) asm volatile("cp.async.cg.shared.global [%0], [%1], 16;" :: "r"(dst), "l"(src) : "memory")
#define CP_COMMIT()    asm volatile("cp.async.commit_group;" ::: "memory")
#define CP_WAIT1()     asm volatile("cp.async.wait_group 1;" ::: "memory")

__device__ __forceinline__ void ldsm_x4(uint32_t* r, uint32_t addr) {
    asm volatile("ldmatrix.sync.aligned.m8n8.x4.shared.b16 {%0,%1,%2,%3}, [%4];"
        : "=r"(r[0]), "=r"(r[1]), "=r"(r[2]), "=r"(r[3]) : "r"(addr));
}
__device__ __forceinline__ void mma16816(float* d, const uint32_t* a, uint32_t b0, uint32_t b1) {
    asm volatile(
        "mma.sync.aligned.m16n8k16.row.col.f32.bf16.bf16.f32 "
        "{%0,%1,%2,%3}, {%4,%5,%6,%7}, {%8,%9}, {%0,%1,%2,%3};"
        : "+f"(d[0]), "+f"(d[1]), "+f"(d[2]), "+f"(d[3])
        : "r"(a[0]), "r"(a[1]), "r"(a[2]), "r"(a[3]), "r"(b0), "r"(b1));
}

// ---------------------------------------------------------------------------
// Prep: split w_in into bf16 hi/lo, [h][kp], zero pad k>=700
__global__ void prep_w(const float* __restrict__ w_in) {
    int idx = blockIdx.x * blockDim.x + threadIdx.x;
    if (idx >= HH * CP) return;
    int h = idx / CP;
    int k = idx - h * CP;
    float v = (k < CC) ? w_in[h * CC + k] : 0.f;
    __nv_bfloat16 hi = __float2bfloat16(v);
    g_wh[idx] = hi;
    g_wl[idx] = __float2bfloat16(v - __bfloat162float(hi));
}

// Prep: transpose w_rec -> fp16 [j][h]; transpose w_out -> [j][o]; zero flags
__global__ void prep_wrec_wout(const float* __restrict__ w_rec,
                               const float* __restrict__ w_out) {
    int idx = blockIdx.x * blockDim.x + threadIdx.x;
    if (idx < HH * HH) {
        int j = idx >> 10;
        int h = idx & 1023;
        g_wrecH[idx] = __float2half(w_rec[h * HH + j]);
    }
    if (idx < HH * OO) {
        int j = idx / OO;
        int o = idx - j * OO;
        g_woutT[idx] = w_out[o * HH + j];
    }
    if (idx < TT) g_done[idx] = 0;
}

// ---------------------------------------------------------------------------
// build_xd tiled: XT=64 (47KB smem -> 4 CTAs/SM), 2 cols per thread (float2).
#define XT 64
#define XC 128
#define XROWS (XT + 30)     // 94
#define XD_SMEM (XROWS * XC * 4)   // 48128 B

__global__ __launch_bounds__(256) void build_xd(const float* __restrict__ x,
                                                const int* __restrict__ delays) {
    extern __shared__ float sx[];   // [XROWS][XC]
    __shared__ int sd[XC];

    const int c0 = blockIdx.x * XC;
    const int t0 = blockIdx.y * XT;
    const int b  = blockIdx.z;
    const int tid = threadIdx.x;

    if (tid < XC) {
        int c = c0 + tid;
        sd[tid] = (c < CC) ? delays[c] : 0;
    }

    // load tile rows t0-30 .. t0+XT-1 as float2 (CC even -> pairs never straddle)
    const float* xb = x + (size_t)b * TT * CC;
    #pragma unroll
    for (int it = 0; it < 24; ++it) {
        int idx = it * 256 + tid;                 // pair index, total 94*64=6016
        if (idx >= XROWS * (XC / 2)) break;
        int row = idx >> 6;                        // /64
        int col = (idx & 63) * 2;
        int g = t0 - 30 + row;
        int c = c0 + col;
        float2 v = make_float2(0.f, 0.f);
        if (g >= 0 && g < TT && c < CC)
            v = *(const float2*)&xb[(size_t)g * CC + c];   // c+1 <= 699 < CC
        *(float2*)&sx[row * XC + col] = v;
    }
    __syncthreads();

    // write delayed outputs, 2 cols/thread, packed bf16x2 stores
    #pragma unroll
    for (int it = 0; it < 16; ++it) {
        int idx = it * 256 + tid;                 // pair index, total 64*64=4096
        int tt = idx >> 6;
        int col = (idx & 63) * 2;
        int t = t0 + tt;
        if (t >= TT || c0 + col >= CP) continue;  // CP even: pair fully in/out
        float v0 = sx[(tt + 30 - sd[col]) * XC + col];
        float v1 = sx[(tt + 30 - sd[col + 1]) * XC + col + 1];
        __nv_bfloat16 h0 = __float2bfloat16(v0);
        __nv_bfloat16 h1 = __float2bfloat16(v1);
        __nv_bfloat16 l0 = __float2bfloat16(v0 - __bfloat162float(h0));
        __nv_bfloat16 l1 = __float2bfloat16(v1 - __bfloat162float(h1));
        size_t o = (size_t)(t * BB + b) * CP + c0 + col;   // even -> 4B aligned
        __nv_bfloat162 hh; hh.x = h0; hh.y = h1;
        __nv_bfloat162 ll; ll.x = l0; ll.y = l1;
        *(__nv_bfloat162*)&g_xh[o] = hh;
        *(__nv_bfloat162*)&g_xl[o] = ll;
    }
}

// ---------------------------------------------------------------------------
// Fused kernel: bids 0..63 = SNN consumers (2 batches each), bids 64..4063 =
// GEMM producers (R5-config GEMM, tile t = gid>>3). 256 thr, 80KB smem, 2/SM.
#define T_STRIDE 80
#define TILE_BYTES 10240
#define BUF_BYTES  40960
#define FUSED_SMEM 81920
#define NCHUNK 22          // 704/32
#define NGTILE_N 8
#define NSNN 64            // SNN CTAs (2 batches each)

__device__ __forceinline__ void gemm_body(char* smem, int gid) {
    const uint32_t sb = smem_u32(smem);
    const int tid = threadIdx.x;
    const int lane = tid & 31;
    const int wid = tid >> 5;
    const int wm = wid & 3;
    const int wn = wid >> 2;
    const int by = gid >> 3;       // timestep t
    const int Nb = (gid & 7) * 128;
    const int Mb = by * 128;

    float d[2][8][4];
    #pragma unroll
    for (int i = 0; i < 2; i++)
        #pragma unroll
        for (int j = 0; j < 8; j++)
            #pragma unroll
            for (int q = 0; q < 4; q++) d[i][j][q] = 0.f;

    auto load_chunk = [&](int kc, int buf) {
        const int k0 = kc * 32;
        #pragma unroll
        for (int j = 0; j < 2; ++j) {
            int i = tid + 256 * j;
            int r = i >> 2, c = i & 3;
            uint32_t doff = (uint32_t)(r * T_STRIDE + c * 16);
            size_t aoff = (size_t)(Mb + r) * CP + k0 + c * 8;
            size_t boff = (size_t)(Nb + r) * CP + k0 + c * 8;
            uint32_t base = sb + buf * BUF_BYTES + doff;
            CP16(base,                  g_xh + aoff);
            CP16(base + TILE_BYTES,     g_xl + aoff);
            CP16(base + 2 * TILE_BYTES, g_wh + boff);
            CP16(base + 3 * TILE_BYTES, g_wl + boff);
        }
    };

    load_chunk(0, 0); CP_COMMIT();
    load_chunk(1, 1); CP_COMMIT();

    const uint32_t a_row = (uint32_t)(wm * 32 + (lane & 15));
    const uint32_t a_kb  = (uint32_t)((lane >> 4) * 16);
    const uint32_t b_row = (uint32_t)(wn * 64 + (lane & 7) + ((lane & 16) ? 8 : 0));
    const uint32_t b_kb  = (uint32_t)(((lane >> 3) & 1) * 16);

    for (int kc = 0; kc < NCHUNK; ++kc) {
        const int buf = kc & 1;
        CP_WAIT1();
        __syncthreads();
        const uint32_t Ah = sb + buf * BUF_BYTES;
        const uint32_t Al = Ah + TILE_BYTES;
        const uint32_t Bh = Ah + 2 * TILE_BYTES;
        const uint32_t Bl = Ah + 3 * TILE_BYTES;

        #pragma unroll
        for (int kk = 0; kk < 2; ++kk) {
            const uint32_t kbase = (uint32_t)(kk * 32);
            uint32_t ah[2][4], al[2][4];
            #pragma unroll
            for (int mf = 0; mf < 2; ++mf) {
                uint32_t ao = (a_row + mf * 16) * T_STRIDE + kbase + a_kb;
                ldsm_x4(ah[mf], Ah + ao);
                ldsm_x4(al[mf], Al + ao);
            }
            uint32_t bh[4][4], bl[4][4];
            #pragma unroll
            for (int nb = 0; nb < 4; ++nb) {
                uint32_t bo = (b_row + nb * 16) * T_STRIDE + kbase + b_kb;
                ldsm_x4(bh[nb], Bh + bo);
                ldsm_x4(bl[nb], Bl + bo);
            }
            #pragma unroll
            for (int mf = 0; mf < 2; ++mf)
                #pragma unroll
                for (int nf = 0; nf < 8; ++nf) {
                    const int nb = nf >> 1, s = (nf & 1) * 2;
                    mma16816(d[mf][nf], ah[mf], bh[nb][s], bh[nb][s + 1]);
                    mma16816(d[mf][nf], ah[mf], bl[nb][s], bl[nb][s + 1]);
                    mma16816(d[mf][nf], al[mf], bh[nb][s], bh[nb][s + 1]);
                }
        }
        __syncthreads();
        if (kc + 2 < NCHUNK) load_chunk(kc + 2, buf);
        CP_COMMIT();
    }

    #pragma unroll
    for (int mf = 0; mf < 2; ++mf) {
        const int row = Mb + wm * 32 + mf * 16 + (lane >> 2);
        #pragma unroll
        for (int nf = 0; nf < 8; ++nf) {
            const int col = Nb + wn * 64 + nf * 8 + (lane & 3) * 2;
            float2* p0 = (float2*)&g_Iin[(size_t)row * HH + col];
            float2* p1 = (float2*)&g_Iin[(size_t)(row + 8) * HH + col];
            *p0 = make_float2(d[mf][nf][0], d[mf][nf][1]);
            *p1 = make_float2(d[mf][nf][2], d[mf][nf][3]);
        }
    }

    __threadfence();
    __syncthreads();
    if (tid == 0) atomicAdd(&g_done[by], 1);
}

// SNN consumer: handles batches b0=2*bid, b1=b0+1. 256 threads, 4 units each.
__device__ __forceinline__ void snn_body(
    char* smem,
    const float* __restrict__ alpha, const float* __restrict__ rho,
    const float* __restrict__ beta_a, const float* __restrict__ beta_out,
    float* __restrict__ out)
{
    const int b0 = blockIdx.x * 2;
    const int b1 = b0 + 1;
    const int tid = threadIdx.x;
    const int lane = tid & 31;
    const int wid = tid >> 5;

    int* act0 = (int*)smem;          // [HH]
    int* act1 = act0 + HH;           // [HH]
    int* cc0  = act1 + HH;           // [32]
    int* cc1  = cc0 + 32;            // [32]

    float v[2][4], aa[2][4], spk[2][4];
    float al[4], rh[4], ba[4];
    #pragma unroll
    for (int k = 0; k < 4; ++k) {
        int h = tid + 256 * k;
        al[k] = alpha[h]; rh[k] = rho[h]; ba[k] = beta_a[h];
        #pragma unroll
        for (int q = 0; q < 2; ++q) { v[q][k] = 0.f; aa[q][k] = 0.f; spk[q][k] = 0.f; }
    }
    float v_out[2] = {0.f, 0.f}, osum[2] = {0.f, 0.f}, bo = 0.f;
    if (tid < OO) bo = beta_out[tid];
    int n_act[2] = {0, 0};

    const __half* __restrict__ wr = g_wrecH;

    for (int t = 0; t < TT; ++t) {
        if (tid == 0) {
            int dv;
            do {
                asm volatile("ld.acquire.gpu.global.b32 %0, [%1];"
                             : "=r"(dv) : "l"(&g_done[t]) : "memory");
                if (dv < NGTILE_N) __nanosleep(200);
            } while (dv < NGTILE_N);
        }
        __syncthreads();

        float Icur[2][4];
        {
            const float* r0 = &g_Iin[(size_t)(t * BB + b0) * HH];
            const float* r1 = &g_Iin[(size_t)(t * BB + b1) * HH];
            #pragma unroll
            for (int k = 0; k < 4; ++k) {
                Icur[0][k] = r0[tid + 256 * k];
                Icur[1][k] = r1[tid + 256 * k];
            }
        }

        // sparse recurrent gathers (independent loops -> good MLP)
        float Irec[2][4] = {{0.f,0.f,0.f,0.f},{0.f,0.f,0.f,0.f}};
        for (int i = 0; i < n_act[0]; ++i) {
            const __half* row = wr + (size_t)act0[i] * HH + tid;
            #pragma unroll
            for (int k = 0; k < 4; ++k) Irec[0][k] += __half2float(row[256 * k]);
        }
        for (int i = 0; i < n_act[1]; ++i) {
            const __half* row = wr + (size_t)act1[i] * HH + tid;
            #pragma unroll
            for (int k = 0; k < 4; ++k) Irec[1][k] += __half2float(row[256 * k]);
        }

        // LIF update both batches
        float spkn[2][4];
        #pragma unroll
        for (int q = 0; q < 2; ++q)
            #pragma unroll
            for (int k = 0; k < 4; ++k) {
                float I1 = Icur[q][k] + Irec[q][k];
                float vn = al[k] * v[q][k] * (1.f - spk[q][k]) + (1.f - al[k]) * (I1 - aa[q][k]);
                spkn[q][k] = (vn > 1.0f) ? 1.f : 0.f;
                aa[q][k] = rh[k] * aa[q][k] + (1.f - rh[k]) * (ba[k] * vn + spkn[q][k]);
                v[q][k] = vn;
                spk[q][k] = spkn[q][k];
            }

        // compaction (chunk (k,wid) ascending h order), both batches
        unsigned msk[2][4];
        #pragma unroll
        for (int k = 0; k < 4; ++k) {
            msk[0][k] = __ballot_sync(0xffffffffu, spkn[0][k] != 0.f);
            msk[1][k] = __ballot_sync(0xffffffffu, spkn[1][k] != 0.f);
            if (lane == 0) {
                cc0[k * 8 + wid] = __popc(msk[0][k]);
                cc1[k * 8 + wid] = __popc(msk[1][k]);
            }
        }
        __syncthreads();      // counts visible; old act reads done
        {
            int c0v = cc0[lane], c1v = cc1[lane];
            int i0 = c0v, i1 = c1v;
            #pragma unroll
            for (int dd = 1; dd < 32; dd <<= 1) {
                int y0 = __shfl_up_sync(0xffffffffu, i0, dd);
                int y1 = __shfl_up_sync(0xffffffffu, i1, dd);
                if (lane >= dd) { i0 += y0; i1 += y1; }
            }
            int e0 = i0 - c0v, e1 = i1 - c1v;
            n_act[0] = __shfl_sync(0xffffffffu, i0, 31);
            n_act[1] = __shfl_sync(0xffffffffu, i1, 31);
            #pragma unroll
            for (int k = 0; k < 4; ++k) {
                int off0 = __shfl_sync(0xffffffffu, e0, k * 8 + wid);
                int off1 = __shfl_sync(0xffffffffu, e1, k * 8 + wid);
                if (spkn[0][k] != 0.f)
                    act0[off0 + __popc(msk[0][k] & ((1u << lane) - 1u))] = tid + 256 * k;
                if (spkn[1][k] != 0.f)
                    act1[off1 + __popc(msk[1][k] & ((1u << lane) - 1u))] = tid + 256 * k;
            }
        }
        __syncthreads();      // new act ready

        if (tid < OO) {
            float a0 = 0.f, a1 = 0.f;
            for (int i = 0; i < n_act[0]; ++i) a0 += g_woutT[(size_t)act0[i] * OO + tid];
            for (int i = 0; i < n_act[1]; ++i) a1 += g_woutT[(size_t)act1[i] * OO + tid];
            v_out[0] = bo * v_out[0] + (1.f - bo) * a0;
            v_out[1] = bo * v_out[1] + (1.f - bo) * a1;
            osum[0] += v_out[0];
            osum[1] += v_out[1];
        }
    }

    if (tid < OO) {
        out[b0 * OO + tid] = osum[0] * (1.f / (float)TT);
        out[b1 * OO + tid] = osum[1] * (1.f / (float)TT);
    }
}

__global__ __launch_bounds__(256, 2) void fused(
    const float* __restrict__ alpha, const float* __restrict__ rho,
    const float* __restrict__ beta_a, const float* __restrict__ beta_out,
    float* __restrict__ out)
{
    extern __shared__ char smem[];
    if (blockIdx.x < NSNN)
        snn_body(smem, alpha, rho, beta_a, beta_out, out);
    else
        gemm_body(smem, blockIdx.x - NSNN);
}

// ---------------------------------------------------------------------------
extern "C" void kernel_launch(void* const* d_in, const int* in_sizes, int n_in,
                              void* d_out, int out_size)
{
    const float* x        = (const float*)d_in[0];
    const int*   delays   = (const int*)  d_in[1];
    const float* w_in     = (const float*)d_in[2];
    const float* w_rec    = (const float*)d_in[3];
    const float* w_out    = (const float*)d_in[4];
    const float* alpha    = (const float*)d_in[5];
    const float* rho      = (const float*)d_in[6];
    const float* beta_a   = (const float*)d_in[7];
    const float* beta_out = (const float*)d_in[8];
    float* out = (float*)d_out;

    static bool attr_set = false;
    if (!attr_set) {
        cudaFuncSetAttribute(fused, cudaFuncAttributeMaxDynamicSharedMemorySize, FUSED_SMEM);
        cudaFuncSetAttribute(build_xd, cudaFuncAttributeMaxDynamicSharedMemorySize, XD_SMEM);
        attr_set = true;
    }

    prep_w        <<<(HH * CP + 255) / 256, 256>>>(w_in);
    prep_wrec_wout<<<(HH * HH + 255) / 256, 256>>>(w_rec, w_out);
    {
        dim3 grid((CP + XC - 1) / XC, (TT + XT - 1) / XT, BB);  // (6,8,128)
        build_xd<<<grid, 256, XD_SMEM>>>(x, delays);
    }
    fused<<<NSNN + (MM / 128) * (HH / 128), 256, FUSED_SMEM>>>(  // 64 + 4000
        alpha, rho, beta_a, beta_out, out);
}

// round 13
// speedup vs baseline: 1.1247x; 1.1247x over previous
#include <cuda_runtime.h>
#include <cuda_bf16.h>
#include <cuda_fp16.h>
#include <cstdint>

// Problem constants
#define TT   500
#define BB   128
#define CC   700
#define CP   704      // padded K
#define HH   1024
#define OO   20
#define MM   (TT*BB)  // 64000

// ---------------------------------------------------------------------------
// Device scratch
__device__ __nv_bfloat16 g_xh[(size_t)MM * CP];   // delayed input hi
__device__ __nv_bfloat16 g_xl[(size_t)MM * CP];   // delayed input lo
__device__ __nv_bfloat16 g_wh[(size_t)HH * CP];   // w_in hi  [h][k]
__device__ __nv_bfloat16 g_wl[(size_t)HH * CP];   // w_in lo
__device__ __half g_wrecH[(size_t)HH * HH];       // w_rec transposed [j][h], fp16
__device__ float g_woutT[(size_t)HH * OO];        // w_out transposed [j][o]
__device__ float g_Iin[(size_t)MM * HH];          // I_in[m][h]
__device__ int   g_done[TT];                      // per-timestep tile counters

// ---------------------------------------------------------------------------
__device__ __forceinline__ uint32_t smem_u32(const void* p) {
    uint32_t a;
    asm("{ .reg .u64 t; cvta.to.shared.u64 t, %1; cvt.u32.u64 %0, t; }" : "=r"(a) : "l"(p));
    return a;
}
#define CP16(dst, src) asm volatile("cp.async.cg.shared.global [%0], [%1], 16;" :: "r"(dst), "l"(src) : "memory")
#define CP_COMMIT()    asm volatile("cp.async.commit_group;" ::: "memory")
#define CP_WAIT1()     asm volatile("cp.async.wait_group 1;" ::: "memory")

__device__ __forceinline__ void ldsm_x4(uint32_t* r, uint32_t addr) {
    asm volatile("ldmatrix.sync.aligned.m8n8.x4.shared.b16 {%0,%1,%2,%3}, [%4];"
        : "=r"(r[0]), "=r"(r[1]), "=r"(r[2]), "=r"(r[3]) : "r"(addr));
}
__device__ __forceinline__ void mma16816(float* d, const uint32_t* a, uint32_t b0, uint32_t b1) {
    asm volatile(
        "mma.sync.aligned.m16n8k16.row.col.f32.bf16.bf16.f32 "
        "{%0,%1,%2,%3}, {%4,%5,%6,%7}, {%8,%9}, {%0,%1,%2,%3};"
        : "+f"(d[0]), "+f"(d[1]), "+f"(d[2]), "+f"(d[3])
        : "r"(a[0]), "r"(a[1]), "r"(a[2]), "r"(a[3]), "r"(b0), "r"(b1));
}

// ---------------------------------------------------------------------------
// Prep: split w_in into bf16 hi/lo, [h][kp], zero pad k>=700
__global__ void prep_w(const float* __restrict__ w_in) {
    int idx = blockIdx.x * blockDim.x + threadIdx.x;
    if (idx >= HH * CP) return;
    int h = idx / CP;
    int k = idx - h * CP;
    float v = (k < CC) ? w_in[h * CC + k] : 0.f;
    __nv_bfloat16 hi = __float2bfloat16(v);
    g_wh[idx] = hi;
    g_wl[idx] = __float2bfloat16(v - __bfloat162float(hi));
}

// Prep: transpose w_rec -> fp16 [j][h]; transpose w_out -> [j][o]; zero flags
__global__ void prep_wrec_wout(const float* __restrict__ w_rec,
                               const float* __restrict__ w_out) {
    int idx = blockIdx.x * blockDim.x + threadIdx.x;
    if (idx < HH * HH) {
        int j = idx >> 10;
        int h = idx & 1023;
        g_wrecH[idx] = __float2half(w_rec[h * HH + j]);
    }
    if (idx < HH * OO) {
        int j = idx / OO;
        int o = idx - j * OO;
        g_woutT[idx] = w_out[o * HH + j];
    }
    if (idx < TT) g_done[idx] = 0;
}

// ---------------------------------------------------------------------------
// build_xd tiled: XT=64 (47KB smem -> 4 CTAs/SM), 2 cols per thread (float2).
// (kept from R12 — removed ~70us vs the R11 version)
#define XT 64
#define XC 128
#define XROWS (XT + 30)     // 94
#define XD_SMEM (XROWS * XC * 4)   // 48128 B

__global__ __launch_bounds__(256) void build_xd(const float* __restrict__ x,
                                                const int* __restrict__ delays) {
    extern __shared__ float sx[];   // [XROWS][XC]
    __shared__ int sd[XC];

    const int c0 = blockIdx.x * XC;
    const int t0 = blockIdx.y * XT;
    const int b  = blockIdx.z;
    const int tid = threadIdx.x;

    if (tid < XC) {
        int c = c0 + tid;
        sd[tid] = (c < CC) ? delays[c] : 0;
    }

    const float* xb = x + (size_t)b * TT * CC;
    #pragma unroll
    for (int it = 0; it < 24; ++it) {
        int idx = it * 256 + tid;
        if (idx >= XROWS * (XC / 2)) break;
        int row = idx >> 6;
        int col = (idx & 63) * 2;
        int g = t0 - 30 + row;
        int c = c0 + col;
        float2 v = make_float2(0.f, 0.f);
        if (g >= 0 && g < TT && c < CC)
            v = *(const float2*)&xb[(size_t)g * CC + c];
        *(float2*)&sx[row * XC + col] = v;
    }
    __syncthreads();

    #pragma unroll
    for (int it = 0; it < 16; ++it) {
        int idx = it * 256 + tid;
        int tt = idx >> 6;
        int col = (idx & 63) * 2;
        int t = t0 + tt;
        if (t >= TT || c0 + col >= CP) continue;
        float v0 = sx[(tt + 30 - sd[col]) * XC + col];
        float v1 = sx[(tt + 30 - sd[col + 1]) * XC + col + 1];
        __nv_bfloat16 h0 = __float2bfloat16(v0);
        __nv_bfloat16 h1 = __float2bfloat16(v1);
        __nv_bfloat16 l0 = __float2bfloat16(v0 - __bfloat162float(h0));
        __nv_bfloat16 l1 = __float2bfloat16(v1 - __bfloat162float(h1));
        size_t o = (size_t)(t * BB + b) * CP + c0 + col;
        __nv_bfloat162 hh; hh.x = h0; hh.y = h1;
        __nv_bfloat162 ll; ll.x = l0; ll.y = l1;
        *(__nv_bfloat162*)&g_xh[o] = hh;
        *(__nv_bfloat162*)&g_xl[o] = ll;
    }
}

// ---------------------------------------------------------------------------
// Fused kernel: bids 0..127 = SNN consumers (1 batch each — R11 proven config),
// bids 128..4127 = GEMM producers. 256 thr, 80KB smem, 2 CTAs/SM.
#define T_STRIDE 80
#define TILE_BYTES 10240
#define BUF_BYTES  40960
#define FUSED_SMEM 81920
#define NCHUNK 22          // 704/32
#define NGTILE_N 8
#define NSNN 128

__device__ __forceinline__ void gemm_body(char* smem, int gid) {
    const uint32_t sb = smem_u32(smem);
    const int tid = threadIdx.x;
    const int lane = tid & 31;
    const int wid = tid >> 5;
    const int wm = wid & 3;
    const int wn = wid >> 2;
    const int by = gid >> 3;       // timestep t
    const int Nb = (gid & 7) * 128;
    const int Mb = by * 128;

    float d[2][8][4];
    #pragma unroll
    for (int i = 0; i < 2; i++)
        #pragma unroll
        for (int j = 0; j < 8; j++)
            #pragma unroll
            for (int q = 0; q < 4; q++) d[i][j][q] = 0.f;

    auto load_chunk = [&](int kc, int buf) {
        const int k0 = kc * 32;
        #pragma unroll
        for (int j = 0; j < 2; ++j) {
            int i = tid + 256 * j;
            int r = i >> 2, c = i & 3;
            uint32_t doff = (uint32_t)(r * T_STRIDE + c * 16);
            size_t aoff = (size_t)(Mb + r) * CP + k0 + c * 8;
            size_t boff = (size_t)(Nb + r) * CP + k0 + c * 8;
            uint32_t base = sb + buf * BUF_BYTES + doff;
            CP16(base,                  g_xh + aoff);
            CP16(base + TILE_BYTES,     g_xl + aoff);
            CP16(base + 2 * TILE_BYTES, g_wh + boff);
            CP16(base + 3 * TILE_BYTES, g_wl + boff);
        }
    };

    load_chunk(0, 0); CP_COMMIT();
    load_chunk(1, 1); CP_COMMIT();

    const uint32_t a_row = (uint32_t)(wm * 32 + (lane & 15));
    const uint32_t a_kb  = (uint32_t)((lane >> 4) * 16);
    const uint32_t b_row = (uint32_t)(wn * 64 + (lane & 7) + ((lane & 16) ? 8 : 0));
    const uint32_t b_kb  = (uint32_t)(((lane >> 3) & 1) * 16);

    for (int kc = 0; kc < NCHUNK; ++kc) {
        const int buf = kc & 1;
        CP_WAIT1();
        __syncthreads();
        const uint32_t Ah = sb + buf * BUF_BYTES;
        const uint32_t Al = Ah + TILE_BYTES;
        const uint32_t Bh = Ah + 2 * TILE_BYTES;
        const uint32_t Bl = Ah + 3 * TILE_BYTES;

        #pragma unroll
        for (int kk = 0; kk < 2; ++kk) {
            const uint32_t kbase = (uint32_t)(kk * 32);
            uint32_t ah[2][4], al[2][4];
            #pragma unroll
            for (int mf = 0; mf < 2; ++mf) {
                uint32_t ao = (a_row + mf * 16) * T_STRIDE + kbase + a_kb;
                ldsm_x4(ah[mf], Ah + ao);
                ldsm_x4(al[mf], Al + ao);
            }
            uint32_t bh[4][4], bl[4][4];
            #pragma unroll
            for (int nb = 0; nb < 4; ++nb) {
                uint32_t bo = (b_row + nb * 16) * T_STRIDE + kbase + b_kb;
                ldsm_x4(bh[nb], Bh + bo);
                ldsm_x4(bl[nb], Bl + bo);
            }
            #pragma unroll
            for (int mf = 0; mf < 2; ++mf)
                #pragma unroll
                for (int nf = 0; nf < 8; ++nf) {
                    const int nb = nf >> 1, s = (nf & 1) * 2;
                    mma16816(d[mf][nf], ah[mf], bh[nb][s], bh[nb][s + 1]);
                    mma16816(d[mf][nf], ah[mf], bl[nb][s], bl[nb][s + 1]);
                    mma16816(d[mf][nf], al[mf], bh[nb][s], bh[nb][s + 1]);
                }
        }
        __syncthreads();
        if (kc + 2 < NCHUNK) load_chunk(kc + 2, buf);
        CP_COMMIT();
    }

    #pragma unroll
    for (int mf = 0; mf < 2; ++mf) {
        const int row = Mb + wm * 32 + mf * 16 + (lane >> 2);
        #pragma unroll
        for (int nf = 0; nf < 8; ++nf) {
            const int col = Nb + wn * 64 + nf * 8 + (lane & 3) * 2;
            float2* p0 = (float2*)&g_Iin[(size_t)row * HH + col];
            float2* p1 = (float2*)&g_Iin[(size_t)(row + 8) * HH + col];
            *p0 = make_float2(d[mf][nf][0], d[mf][nf][1]);
            *p1 = make_float2(d[mf][nf][2], d[mf][nf][3]);
        }
    }

    __threadfence();
    __syncthreads();
    if (tid == 0) atomicAdd(&g_done[by], 1);
}

// SNN consumer: 1 batch per CTA (proven R11 config). 256 threads, 4 units each.
__device__ __forceinline__ void snn_body(
    char* smem,
    const float* __restrict__ alpha, const float* __restrict__ rho,
    const float* __restrict__ beta_a, const float* __restrict__ beta_out,
    float* __restrict__ out)
{
    const int b = blockIdx.x;
    const int tid = threadIdx.x;
    const int lane = tid & 31;
    const int wid = tid >> 5;

    int* act = (int*)smem;              // [HH]
    int* chunk_cnt = act + HH;          // [32]

    float v[4], aa[4], spk[4], al[4], rh[4], ba[4];
    #pragma unroll
    for (int k = 0; k < 4; ++k) {
        int h = tid + 256 * k;
        v[k] = 0.f; aa[k] = 0.f; spk[k] = 0.f;
        al[k] = alpha[h]; rh[k] = rho[h]; ba[k] = beta_a[h];
    }
    float v_out = 0.f, osum = 0.f, bo = 0.f;
    if (tid < OO) bo = beta_out[tid];
    int n_act = 0;

    const __half* __restrict__ wr = g_wrecH;

    for (int t = 0; t < TT; ++t) {
        if (tid == 0) {
            int dv;
            do {
                asm volatile("ld.acquire.gpu.global.b32 %0, [%1];"
                             : "=r"(dv) : "l"(&g_done[t]) : "memory");
                if (dv < NGTILE_N) __nanosleep(200);
            } while (dv < NGTILE_N);
        }
        __syncthreads();

        const float* Irow = &g_Iin[(size_t)(t * BB + b) * HH];
        float Icur[4];
        #pragma unroll
        for (int k = 0; k < 4; ++k) Icur[k] = Irow[tid + 256 * k];

        float Irec[4] = {0.f, 0.f, 0.f, 0.f};
        for (int i = 0; i < n_act; ++i) {
            const __half* row = wr + (size_t)act[i] * HH + tid;
            #pragma unroll
            for (int k = 0; k < 4; ++k)
                Irec[k] += __half2float(row[256 * k]);
        }

        float spkn[4];
        #pragma unroll
        for (int k = 0; k < 4; ++k) {
            float I1 = Icur[k] + Irec[k];
            float vn = al[k] * v[k] * (1.f - spk[k]) + (1.f - al[k]) * (I1 - aa[k]);
            spkn[k] = (vn > 1.0f) ? 1.f : 0.f;
            aa[k] = rh[k] * aa[k] + (1.f - rh[k]) * (ba[k] * vn + spkn[k]);
            v[k] = vn;
            spk[k] = spkn[k];
        }

        unsigned msk[4];
        #pragma unroll
        for (int k = 0; k < 4; ++k) {
            msk[k] = __ballot_sync(0xffffffffu, spkn[k] != 0.f);
            if (lane == 0) chunk_cnt[k * 8 + wid] = __popc(msk[k]);
        }
        __syncthreads();
        {
            int cnt = chunk_cnt[lane];
            int incl = cnt;
            #pragma unroll
            for (int dd = 1; dd < 32; dd <<= 1) {
                int y = __shfl_up_sync(0xffffffffu, incl, dd);
                if (lane >= dd) incl += y;
            }
            int excl = incl - cnt;
            n_act = __shfl_sync(0xffffffffu, incl, 31);
            #pragma unroll
            for (int k = 0; k < 4; ++k) {
                int off = __shfl_sync(0xffffffffu, excl, k * 8 + wid);
                if (spkn[k] != 0.f)
                    act[off + __popc(msk[k] & ((1u << lane) - 1u))] = tid + 256 * k;
            }
        }
        __syncthreads();

        if (tid < OO) {
            float accum = 0.f;
            for (int i = 0; i < n_act; ++i)
                accum += g_woutT[(size_t)act[i] * OO + tid];
            v_out = bo * v_out + (1.f - bo) * accum;
            osum += v_out;
        }
    }

    if (tid < OO) out[b * OO + tid] = osum * (1.f / (float)TT);
}

__global__ __launch_bounds__(256, 2) void fused(
    const float* __restrict__ alpha, const float* __restrict__ rho,
    const float* __restrict__ beta_a, const float* __restrict__ beta_out,
    float* __restrict__ out)
{
    extern __shared__ char smem[];
    if (blockIdx.x < NSNN)
        snn_body(smem, alpha, rho, beta_a, beta_out, out);
    else
        gemm_body(smem, blockIdx.x - NSNN);
}

// ---------------------------------------------------------------------------
extern "C" void kernel_launch(void* const* d_in, const int* in_sizes, int n_in,
                              void* d_out, int out_size)
{
    const float* x        = (const float*)d_in[0];
    const int*   delays   = (const int*)  d_in[1];
    const float* w_in     = (const float*)d_in[2];
    const float* w_rec    = (const float*)d_in[3];
    const float* w_out    = (const float*)d_in[4];
    const float* alpha    = (const float*)d_in[5];
    const float* rho      = (const float*)d_in[6];
    const float* beta_a   = (const float*)d_in[7];
    const float* beta_out = (const float*)d_in[8];
    float* out = (float*)d_out;

    static bool attr_set = false;
    if (!attr_set) {
        cudaFuncSetAttribute(fused, cudaFuncAttributeMaxDynamicSharedMemorySize, FUSED_SMEM);
        cudaFuncSetAttribute(build_xd, cudaFuncAttributeMaxDynamicSharedMemorySize, XD_SMEM);
        attr_set = true;
    }

    prep_w        <<<(HH * CP + 255) / 256, 256>>>(w_in);
    prep_wrec_wout<<<(HH * HH + 255) / 256, 256>>>(w_rec, w_out);
    {
        dim3 grid((CP + XC - 1) / XC, (TT + XT - 1) / XT, BB);  // (6,8,128)
        build_xd<<<grid, 256, XD_SMEM>>>(x, delays);
    }
    fused<<<NSNN + (MM / 128) * (HH / 128), 256, FUSED_SMEM>>>(  // 128 + 4000
        alpha, rho, beta_a, beta_out, out);
}

// round 14
// speedup vs baseline: 1.1280x; 1.0029x over previous
#include <cuda_runtime.h>
#include <cuda_bf16.h>
#include <cuda_fp16.h>
#include <cstdint>

// Problem constants
#define TT   500
#define BB   128
#define CC   700
#define CP   704      // padded K
#define HH   1024
#define OO   20
#define MM   (TT*BB)  // 64000

// ---------------------------------------------------------------------------
// Device scratch
__device__ __nv_bfloat16 g_xh[(size_t)MM * CP];   // delayed input hi
__device__ __nv_bfloat16 g_xl[(size_t)MM * CP];   // delayed input lo
__device__ __nv_bfloat16 g_wh[(size_t)HH * CP];   // w_in hi  [h][k]
__device__ __nv_bfloat16 g_wl[(size_t)HH * CP];   // w_in lo
__device__ __half g_wrecH[(size_t)HH * HH];       // w_rec transposed [j][h], fp16
__device__ float g_woutT[(size_t)HH * OO];        // w_out transposed [j][o]
__device__ float g_Iin[(size_t)MM * HH];          // I_in[m][h]
__device__ int   g_done[TT];                      // per-timestep tile counters

// ---------------------------------------------------------------------------
__device__ __forceinline__ uint32_t smem_u32(const void* p) {
    uint32_t a;
    asm("{ .reg .u64 t; cvta.to.shared.u64 t, %1; cvt.u32.u64 %0, t; }" : "=r"(a) : "l"(p));
    return a;
}
#define CP16(dst, src) asm volatile("cp.async.cg.shared.global [%0], [%1], 16;" :: "r"(dst), "l"(src) : "memory")
#define CP_COMMIT()    asm volatile("cp.async.commit_group;" ::: "memory")
#define CP_WAIT1()     asm volatile("cp.async.wait_group 1;" ::: "memory")

__device__ __forceinline__ void ldsm_x4(uint32_t* r, uint32_t addr) {
    asm volatile("ldmatrix.sync.aligned.m8n8.x4.shared.b16 {%0,%1,%2,%3}, [%4];"
        : "=r"(r[0]), "=r"(r[1]), "=r"(r[2]), "=r"(r[3]) : "r"(addr));
}
__device__ __forceinline__ void mma16816(float* d, const uint32_t* a, uint32_t b0, uint32_t b1) {
    asm volatile(
        "mma.sync.aligned.m16n8k16.row.col.f32.bf16.bf16.f32 "
        "{%0,%1,%2,%3}, {%4,%5,%6,%7}, {%8,%9}, {%0,%1,%2,%3};"
        : "+f"(d[0]), "+f"(d[1]), "+f"(d[2]), "+f"(d[3])
        : "r"(a[0]), "r"(a[1]), "r"(a[2]), "r"(a[3]), "r"(b0), "r"(b1));
}

// ---------------------------------------------------------------------------
// Prep: split w_in into bf16 hi/lo, [h][kp], zero pad k>=700
__global__ void prep_w(const float* __restrict__ w_in) {
    int idx = blockIdx.x * blockDim.x + threadIdx.x;
    if (idx >= HH * CP) return;
    int h = idx / CP;
    int k = idx - h * CP;
    float v = (k < CC) ? w_in[h * CC + k] : 0.f;
    __nv_bfloat16 hi = __float2bfloat16(v);
    g_wh[idx] = hi;
    g_wl[idx] = __float2bfloat16(v - __bfloat162float(hi));
}

// Prep: transpose w_rec -> fp16 [j][h]; transpose w_out -> [j][o]; zero flags
__global__ void prep_wrec_wout(const float* __restrict__ w_rec,
                               const float* __restrict__ w_out) {
    int idx = blockIdx.x * blockDim.x + threadIdx.x;
    if (idx < HH * HH) {
        int j = idx >> 10;
        int h = idx & 1023;
        g_wrecH[idx] = __float2half(w_rec[h * HH + j]);
    }
    if (idx < HH * OO) {
        int j = idx / OO;
        int o = idx - j * OO;
        g_woutT[idx] = w_out[o * HH + j];
    }
    if (idx < TT) g_done[idx] = 0;
}

// ---------------------------------------------------------------------------
// build_xd tiled: XT=64 (47KB smem -> 4 CTAs/SM), 2 cols per thread (float2).
#define XT 64
#define XC 128
#define XROWS (XT + 30)     // 94
#define XD_SMEM (XROWS * XC * 4)   // 48128 B

__global__ __launch_bounds__(256) void build_xd(const float* __restrict__ x,
                                                const int* __restrict__ delays) {
    extern __shared__ float sx[];
    __shared__ int sd[XC];

    const int c0 = blockIdx.x * XC;
    const int t0 = blockIdx.y * XT;
    const int b  = blockIdx.z;
    const int tid = threadIdx.x;

    if (tid < XC) {
        int c = c0 + tid;
        sd[tid] = (c < CC) ? delays[c] : 0;
    }

    const float* xb = x + (size_t)b * TT * CC;
    #pragma unroll
    for (int it = 0; it < 24; ++it) {
        int idx = it * 256 + tid;
        if (idx >= XROWS * (XC / 2)) break;
        int row = idx >> 6;
        int col = (idx & 63) * 2;
        int g = t0 - 30 + row;
        int c = c0 + col;
        float2 v = make_float2(0.f, 0.f);
        if (g >= 0 && g < TT && c < CC)
            v = *(const float2*)&xb[(size_t)g * CC + c];
        *(float2*)&sx[row * XC + col] = v;
    }
    __syncthreads();

    #pragma unroll
    for (int it = 0; it < 16; ++it) {
        int idx = it * 256 + tid;
        int tt = idx >> 6;
        int col = (idx & 63) * 2;
        int t = t0 + tt;
        if (t >= TT || c0 + col >= CP) continue;
        float v0 = sx[(tt + 30 - sd[col]) * XC + col];
        float v1 = sx[(tt + 30 - sd[col + 1]) * XC + col + 1];
        __nv_bfloat16 h0 = __float2bfloat16(v0);
        __nv_bfloat16 h1 = __float2bfloat16(v1);
        __nv_bfloat16 l0 = __float2bfloat16(v0 - __bfloat162float(h0));
        __nv_bfloat16 l1 = __float2bfloat16(v1 - __bfloat162float(h1));
        size_t o = (size_t)(t * BB + b) * CP + c0 + col;
        __nv_bfloat162 hh; hh.x = h0; hh.y = h1;
        __nv_bfloat162 ll; ll.x = l0; ll.y = l1;
        *(__nv_bfloat162*)&g_xh[o] = hh;
        *(__nv_bfloat162*)&g_xl[o] = ll;
    }
}

// ---------------------------------------------------------------------------
// Fused kernel: bids 0..127 = SNN consumers (1 batch each), bids 128..4127 =
// GEMM producers. 256 thr, 80KB smem, 2 CTAs/SM.
#define T_STRIDE 80
#define TILE_BYTES 10240
#define BUF_BYTES  40960
#define FUSED_SMEM 81920
#define NCHUNK 22          // 704/32
#define NGTILE_N 8
#define NSNN 128

__device__ __forceinline__ void gemm_body(char* smem, int gid) {
    const uint32_t sb = smem_u32(smem);
    const int tid = threadIdx.x;
    const int lane = tid & 31;
    const int wid = tid >> 5;
    const int wm = wid & 3;
    const int wn = wid >> 2;
    const int by = gid >> 3;       // timestep t
    const int Nb = (gid & 7) * 128;
    const int Mb = by * 128;

    float d[2][8][4];
    #pragma unroll
    for (int i = 0; i < 2; i++)
        #pragma unroll
        for (int j = 0; j < 8; j++)
            #pragma unroll
            for (int q = 0; q < 4; q++) d[i][j][q] = 0.f;

    auto load_chunk = [&](int kc, int buf) {
        const int k0 = kc * 32;
        #pragma unroll
        for (int j = 0; j < 2; ++j) {
            int i = tid + 256 * j;
            int r = i >> 2, c = i & 3;
            uint32_t doff = (uint32_t)(r * T_STRIDE + c * 16);
            size_t aoff = (size_t)(Mb + r) * CP + k0 + c * 8;
            size_t boff = (size_t)(Nb + r) * CP + k0 + c * 8;
            uint32_t base = sb + buf * BUF_BYTES + doff;
            CP16(base,                  g_xh + aoff);
            CP16(base + TILE_BYTES,     g_xl + aoff);
            CP16(base + 2 * TILE_BYTES, g_wh + boff);
            CP16(base + 3 * TILE_BYTES, g_wl + boff);
        }
    };

    load_chunk(0, 0); CP_COMMIT();
    load_chunk(1, 1); CP_COMMIT();

    const uint32_t a_row = (uint32_t)(wm * 32 + (lane & 15));
    const uint32_t a_kb  = (uint32_t)((lane >> 4) * 16);
    const uint32_t b_row = (uint32_t)(wn * 64 + (lane & 7) + ((lane & 16) ? 8 : 0));
    const uint32_t b_kb  = (uint32_t)(((lane >> 3) & 1) * 16);

    for (int kc = 0; kc < NCHUNK; ++kc) {
        const int buf = kc & 1;
        CP_WAIT1();
        __syncthreads();
        const uint32_t Ah = sb + buf * BUF_BYTES;
        const uint32_t Al = Ah + TILE_BYTES;
        const uint32_t Bh = Ah + 2 * TILE_BYTES;
        const uint32_t Bl = Ah + 3 * TILE_BYTES;

        #pragma unroll
        for (int kk = 0; kk < 2; ++kk) {
            const uint32_t kbase = (uint32_t)(kk * 32);
            uint32_t ah[2][4], al[2][4];
            #pragma unroll
            for (int mf = 0; mf < 2; ++mf) {
                uint32_t ao = (a_row + mf * 16) * T_STRIDE + kbase + a_kb;
                ldsm_x4(ah[mf], Ah + ao);
                ldsm_x4(al[mf], Al + ao);
            }
            uint32_t bh[4][4], bl[4][4];
            #pragma unroll
            for (int nb = 0; nb < 4; ++nb) {
                uint32_t bo = (b_row + nb * 16) * T_STRIDE + kbase + b_kb;
                ldsm_x4(bh[nb], Bh + bo);
                ldsm_x4(bl[nb], Bl + bo);
            }
            #pragma unroll
            for (int mf = 0; mf < 2; ++mf)
                #pragma unroll
                for (int nf = 0; nf < 8; ++nf) {
                    const int nb = nf >> 1, s = (nf & 1) * 2;
                    mma16816(d[mf][nf], ah[mf], bh[nb][s], bh[nb][s + 1]);
                    mma16816(d[mf][nf], ah[mf], bl[nb][s], bl[nb][s + 1]);
                    mma16816(d[mf][nf], al[mf], bh[nb][s], bh[nb][s + 1]);
                }
        }
        __syncthreads();
        if (kc + 2 < NCHUNK) load_chunk(kc + 2, buf);
        CP_COMMIT();
    }

    #pragma unroll
    for (int mf = 0; mf < 2; ++mf) {
        const int row = Mb + wm * 32 + mf * 16 + (lane >> 2);
        #pragma unroll
        for (int nf = 0; nf < 8; ++nf) {
            const int col = Nb + wn * 64 + nf * 8 + (lane & 3) * 2;
            float2* p0 = (float2*)&g_Iin[(size_t)row * HH + col];
            float2* p1 = (float2*)&g_Iin[(size_t)(row + 8) * HH + col];
            *p0 = make_float2(d[mf][nf][0], d[mf][nf][1]);
            *p1 = make_float2(d[mf][nf][2], d[mf][nf][3]);
        }
    }

    __threadfence();
    __syncthreads();
    if (tid == 0) atomicAdd(&g_done[by], 1);
}

// SNN consumer: 1 batch per CTA, CONSECUTIVE unit mapping h = 4*tid..4*tid+3.
// Gather = one LDG.64 per active row per thread (4x fewer load instrs).
__device__ __forceinline__ void snn_body(
    char* smem,
    const float* __restrict__ alpha, const float* __restrict__ rho,
    const float* __restrict__ beta_a, const float* __restrict__ beta_out,
    float* __restrict__ out)
{
    const int b = blockIdx.x;
    const int tid = threadIdx.x;
    const int lane = tid & 31;
    const int wid = tid >> 5;

    int* act  = (int*)smem;             // [HH]
    int* wsum = act + HH;               // [8] per-warp spike counts

    // consecutive params: float4 loads
    float4 al4 = *(const float4*)&alpha[4 * tid];
    float4 rh4 = *(const float4*)&rho[4 * tid];
    float4 ba4 = *(const float4*)&beta_a[4 * tid];
    float al[4] = {al4.x, al4.y, al4.z, al4.w};
    float rh[4] = {rh4.x, rh4.y, rh4.z, rh4.w};
    float ba[4] = {ba4.x, ba4.y, ba4.z, ba4.w};

    float v[4] = {0.f, 0.f, 0.f, 0.f};
    float aa[4] = {0.f, 0.f, 0.f, 0.f};
    float spk[4] = {0.f, 0.f, 0.f, 0.f};
    float v_out = 0.f, osum = 0.f, bo = 0.f;
    if (tid < OO) bo = beta_out[tid];
    int n_act = 0;

    const __half* __restrict__ wr = g_wrecH;

    for (int t = 0; t < TT; ++t) {
        if (tid == 0) {
            int dv;
            do {
                asm volatile("ld.acquire.gpu.global.b32 %0, [%1];"
                             : "=r"(dv) : "l"(&g_done[t]) : "memory");
                if (dv < NGTILE_N) __nanosleep(200);
            } while (dv < NGTILE_N);
        }
        __syncthreads();

        // input current: one float4 per thread, fully coalesced
        float4 Ic = *(const float4*)&g_Iin[(size_t)(t * BB + b) * HH + 4 * tid];
        float Icur[4] = {Ic.x, Ic.y, Ic.z, Ic.w};

        // sparse recurrent gather: one 8B load (4 fp16) per active row
        float Irec[4] = {0.f, 0.f, 0.f, 0.f};
        for (int i = 0; i < n_act; ++i) {
            uint2 w2 = *(const uint2*)(wr + (size_t)act[i] * HH + 4 * tid);
            __half2 p0 = *reinterpret_cast<__half2*>(&w2.x);
            __half2 p1 = *reinterpret_cast<__half2*>(&w2.y);
            Irec[0] += __low2float(p0);
            Irec[1] += __high2float(p0);
            Irec[2] += __low2float(p1);
            Irec[3] += __high2float(p1);
        }

        // LIF update (exact reference math)
        float spkn[4];
        #pragma unroll
        for (int k = 0; k < 4; ++k) {
            float I1 = Icur[k] + Irec[k];
            float vn = al[k] * v[k] * (1.f - spk[k]) + (1.f - al[k]) * (I1 - aa[k]);
            spkn[k] = (vn > 1.0f) ? 1.f : 0.f;
            aa[k] = rh[k] * aa[k] + (1.f - rh[k]) * (ba[k] * vn + spkn[k]);
            v[k] = vn;
            spk[k] = spkn[k];
        }

        // deterministic ascending-h compaction: thread owns 4 consecutive units
        unsigned mybits = (spkn[0] != 0.f ? 1u : 0u) | (spkn[1] != 0.f ? 2u : 0u)
                        | (spkn[2] != 0.f ? 4u : 0u) | (spkn[3] != 0.f ? 8u : 0u);
        int c = __popc(mybits);
        int incl = c;
        #pragma unroll
        for (int dd = 1; dd < 32; dd <<= 1) {
            int y = __shfl_up_sync(0xffffffffu, incl, dd);
            if (lane >= dd) incl += y;
        }
        if (lane == 31) wsum[wid] = incl;
        __syncthreads();                 // wsum visible; old act reads done
        {
            int woffv = 0, tot = 0;
            #pragma unroll
            for (int w = 0; w < 8; ++w) {
                int s = wsum[w];
                if (w < wid) woffv += s;
                tot += s;
            }
            n_act = tot;
            int p = woffv + incl - c;    // exclusive offset for this thread
            int h0 = 4 * tid;
            if (mybits & 1u) act[p++] = h0;
            if (mybits & 2u) act[p++] = h0 + 1;
            if (mybits & 4u) act[p++] = h0 + 2;
            if (mybits & 8u) act[p++] = h0 + 3;
        }
        __syncthreads();                 // new act ready

        // readout over new active list
        if (tid < OO) {
            float accum = 0.f;
            for (int i = 0; i < n_act; ++i)
                accum += g_woutT[(size_t)act[i] * OO + tid];
            v_out = bo * v_out + (1.f - bo) * accum;
            osum += v_out;
        }
    }

    if (tid < OO) out[b * OO + tid] = osum * (1.f / (float)TT);
}

__global__ __launch_bounds__(256, 2) void fused(
    const float* __restrict__ alpha, const float* __restrict__ rho,
    const float* __restrict__ beta_a, const float* __restrict__ beta_out,
    float* __restrict__ out)
{
    extern __shared__ char smem[];
    if (blockIdx.x < NSNN)
        snn_body(smem, alpha, rho, beta_a, beta_out, out);
    else
        gemm_body(smem, blockIdx.x - NSNN);
}

// ---------------------------------------------------------------------------
extern "C" void kernel_launch(void* const* d_in, const int* in_sizes, int n_in,
                              void* d_out, int out_size)
{
    const float* x        = (const float*)d_in[0];
    const int*   delays   = (const int*)  d_in[1];
    const float* w_in     = (const float*)d_in[2];
    const float* w_rec    = (const float*)d_in[3];
    const float* w_out    = (const float*)d_in[4];
    const float* alpha    = (const float*)d_in[5];
    const float* rho      = (const float*)d_in[6];
    const float* beta_a   = (const float*)d_in[7];
    const float* beta_out = (const float*)d_in[8];
    float* out = (float*)d_out;

    static bool attr_set = false;
    if (!attr_set) {
        cudaFuncSetAttribute(fused, cudaFuncAttributeMaxDynamicSharedMemorySize, FUSED_SMEM);
        cudaFuncSetAttribute(build_xd, cudaFuncAttributeMaxDynamicSharedMemorySize, XD_SMEM);
        attr_set = true;
    }

    prep_w        <<<(HH * CP + 255) / 256, 256>>>(w_in);
    prep_wrec_wout<<<(HH * HH + 255) / 256, 256>>>(w_rec, w_out);
    {
        dim3 grid((CP + XC - 1) / XC, (TT + XT - 1) / XT, BB);  // (6,8,128)
        build_xd<<<grid, 256, XD_SMEM>>>(x, delays);
    }
    fused<<<NSNN + (MM / 128) * (HH / 128), 256, FUSED_SMEM>>>(  // 128 + 4000
        alpha, rho, beta_a, beta_out, out);
}